// round 1
// baseline (speedup 1.0000x reference)
#include <cuda_runtime.h>
#include <math.h>

#define T_TOK 4096
#define DIM   1024
#define NE    8
#define NH    2736
#define TK    2

#define BM 64
#define BN 128
#define BK 16

// ---------------- scratch (static device globals; no allocations) ----------------
__device__ int   g_counts[NE];
__device__ int   g_list [NE * T_TOK];   // token index per (expert, slot)
__device__ int   g_kslot[NE * T_TOK];   // destination pair id = t*2+k
__device__ float g_topw [T_TOK * TK];   // softmax weights per (t,k)
__device__ float g_h[(size_t)T_TOK * TK * NH];   // GLU hidden per pair  (~90 MB)
__device__ float g_y[(size_t)T_TOK * TK * DIM];  // expert output per pair (~34 MB)

// ---------------- init: zero expert counters ----------------
__global__ void init_kernel() {
    if (threadIdx.x < NE) g_counts[threadIdx.x] = 0;
}

// ---------------- gating: one warp per token ----------------
__global__ void gate_kernel(const float* __restrict__ x,
                            const float* __restrict__ gw,
                            const float* __restrict__ gb) {
    int lane = threadIdx.x & 31;
    int w    = threadIdx.x >> 5;
    int t    = blockIdx.x * (blockDim.x >> 5) + w;
    if (t >= T_TOK) return;

    float acc[NE];
#pragma unroll
    for (int e = 0; e < NE; e++) acc[e] = 0.f;

    const float* xr = x + (size_t)t * DIM;
    for (int d = lane; d < DIM; d += 32) {
        float xv = __ldg(xr + d);
        const float4* g4 = (const float4*)(gw + d * NE);
        float4 a = __ldg(g4);
        float4 b = __ldg(g4 + 1);
        acc[0] += xv * a.x; acc[1] += xv * a.y; acc[2] += xv * a.z; acc[3] += xv * a.w;
        acc[4] += xv * b.x; acc[5] += xv * b.y; acc[6] += xv * b.z; acc[7] += xv * b.w;
    }
#pragma unroll
    for (int e = 0; e < NE; e++) {
#pragma unroll
        for (int off = 16; off > 0; off >>= 1)
            acc[e] += __shfl_xor_sync(0xffffffffu, acc[e], off);
    }

    if (lane == 0) {
        float v0 = -1e30f, v1 = -1e30f;
        int   i0 = 0,      i1 = 0;
#pragma unroll
        for (int e = 0; e < NE; e++) {
            float v = acc[e] + gb[e];
            if (v > v0)      { v1 = v0; i1 = i0; v0 = v; i0 = e; }
            else if (v > v1) { v1 = v;  i1 = e; }
        }
        float w0 = 1.f / (1.f + expf(v1 - v0));  // softmax over 2
        float w1 = 1.f - w0;
        g_topw[t * 2]     = w0;
        g_topw[t * 2 + 1] = w1;
        int p0 = atomicAdd(&g_counts[i0], 1);
        g_list [i0 * T_TOK + p0] = t;
        g_kslot[i0 * T_TOK + p0] = t * 2;
        int p1 = atomicAdd(&g_counts[i1], 1);
        g_list [i1 * T_TOK + p1] = t;
        g_kslot[i1 * T_TOK + p1] = t * 2 + 1;
    }
}

// ---------------- FFN stage 1: h = silu(x@wg + bg) * (x@w1 + b1), grouped by expert ----------------
// Block: 64 pairs (rows of same expert) x 128 H-cols. Both GEMMs share the gathered x tile.
__global__ __launch_bounds__(256)
void ffn1_kernel(const float* __restrict__ x,
                 const float* __restrict__ wg, const float* __restrict__ bg,
                 const float* __restrict__ w1, const float* __restrict__ b1) {
    int e   = blockIdx.z;
    int cnt = g_counts[e];
    int m0  = blockIdx.y * BM;
    if (m0 >= cnt) return;
    int n0  = blockIdx.x * BN;
    int tid = threadIdx.x;

    __shared__ float sx [BM][BK + 4];
    __shared__ float swg[BK][BN];
    __shared__ float sw1[BK][BN];

    // x-tile load mapping: one row per (tid&63), 4 consecutive k per thread
    int  lm   = tid & 63;
    int  lk   = (tid >> 6) * 4;
    int  row  = m0 + lm;
    bool vrow = row < cnt;
    int  tok  = vrow ? g_list[e * T_TOK + row] : 0;
    const float* xrow = x + (size_t)tok * DIM;

    // weight-tile load mapping: 8 k-rows per pass, 32 float4 across n
    int  wk0  = tid >> 5;         // 0..7
    int  wn   = (tid & 31) * 4;   // 0..124
    bool vn   = (n0 + wn) < NH;   // float4-granular guard (NH%4==0)
    const float* wgE = wg + (size_t)e * DIM * NH;
    const float* w1E = w1 + (size_t)e * DIM * NH;

    float accg[4][8], acc1[4][8];
#pragma unroll
    for (int i = 0; i < 4; i++)
#pragma unroll
        for (int j = 0; j < 8; j++) { accg[i][j] = 0.f; acc1[i][j] = 0.f; }

    int tm = (tid >> 4) * 4;   // 0..60
    int tn = (tid & 15) * 8;   // 0..120

    const float4 z4 = make_float4(0.f, 0.f, 0.f, 0.f);

    for (int k0 = 0; k0 < DIM; k0 += BK) {
        float4 xv = vrow ? *(const float4*)(xrow + k0 + lk) : z4;
        *(float4*)&sx[lm][lk] = xv;
#pragma unroll
        for (int j = 0; j < 2; j++) {
            int kk = wk0 + j * 8;
            float4 gq = vn ? *(const float4*)(wgE + (size_t)(k0 + kk) * NH + n0 + wn) : z4;
            float4 oq = vn ? *(const float4*)(w1E + (size_t)(k0 + kk) * NH + n0 + wn) : z4;
            *(float4*)&swg[kk][wn] = gq;
            *(float4*)&sw1[kk][wn] = oq;
        }
        __syncthreads();
#pragma unroll
        for (int k = 0; k < BK; k++) {
            float a[4];
#pragma unroll
            for (int i = 0; i < 4; i++) a[i] = sx[tm + i][k];
            float4 ga = *(float4*)&swg[k][tn];
            float4 gb4 = *(float4*)&swg[k][tn + 4];
            float4 oa = *(float4*)&sw1[k][tn];
            float4 ob = *(float4*)&sw1[k][tn + 4];
            float bgv[8] = {ga.x, ga.y, ga.z, ga.w, gb4.x, gb4.y, gb4.z, gb4.w};
            float b1v[8] = {oa.x, oa.y, oa.z, oa.w, ob.x, ob.y, ob.z, ob.w};
#pragma unroll
            for (int i = 0; i < 4; i++)
#pragma unroll
                for (int j = 0; j < 8; j++) {
                    accg[i][j] += a[i] * bgv[j];
                    acc1[i][j] += a[i] * b1v[j];
                }
        }
        __syncthreads();
    }

    // epilogue: activation + store to per-pair hidden rows
#pragma unroll
    for (int i = 0; i < 4; i++) {
        int r = m0 + tm + i;
        if (r >= cnt) continue;
        int ks = g_kslot[e * T_TOK + r];
        float* hrow = g_h + (size_t)ks * NH;
#pragma unroll
        for (int j = 0; j < 8; j++) {
            int n = n0 + tn + j;
            if (n < NH) {
                float a = accg[i][j] + bg[e * NH + n];
                float b = acc1[i][j] + b1[e * NH + n];
                float s = a / (1.f + expf(-a));   // silu
                hrow[n] = s * b;
            }
        }
    }
}

// ---------------- FFN stage 2: y = h @ w2 + b2, per pair ----------------
__global__ __launch_bounds__(256)
void ffn2_kernel(const float* __restrict__ w2, const float* __restrict__ b2) {
    int e   = blockIdx.z;
    int cnt = g_counts[e];
    int m0  = blockIdx.y * BM;
    if (m0 >= cnt) return;
    int n0  = blockIdx.x * BN;    // D tiles: exact, no guard
    int tid = threadIdx.x;

    __shared__ float sh[BM][BK + 4];
    __shared__ float sw[BK][BN];

    int  lm   = tid & 63;
    int  lk   = (tid >> 6) * 4;
    int  row  = m0 + lm;
    bool vrow = row < cnt;
    int  ks   = vrow ? g_kslot[e * T_TOK + row] : 0;
    const float* hrow = g_h + (size_t)ks * NH;

    int wk0 = tid >> 5;
    int wn  = (tid & 31) * 4;
    const float* w2E = w2 + (size_t)e * NH * DIM;

    float acc[4][8];
#pragma unroll
    for (int i = 0; i < 4; i++)
#pragma unroll
        for (int j = 0; j < 8; j++) acc[i][j] = 0.f;

    int tm = (tid >> 4) * 4;
    int tn = (tid & 15) * 8;
    const float4 z4 = make_float4(0.f, 0.f, 0.f, 0.f);

    for (int k0 = 0; k0 < NH; k0 += BK) {
        float4 hv = vrow ? *(const float4*)(hrow + k0 + lk) : z4;
        *(float4*)&sh[lm][lk] = hv;
#pragma unroll
        for (int j = 0; j < 2; j++) {
            int kk = wk0 + j * 8;
            *(float4*)&sw[kk][wn] =
                *(const float4*)(w2E + (size_t)(k0 + kk) * DIM + n0 + wn);
        }
        __syncthreads();
#pragma unroll
        for (int k = 0; k < BK; k++) {
            float a[4];
#pragma unroll
            for (int i = 0; i < 4; i++) a[i] = sh[tm + i][k];
            float4 wa = *(float4*)&sw[k][tn];
            float4 wb = *(float4*)&sw[k][tn + 4];
            float wv[8] = {wa.x, wa.y, wa.z, wa.w, wb.x, wb.y, wb.z, wb.w};
#pragma unroll
            for (int i = 0; i < 4; i++)
#pragma unroll
                for (int j = 0; j < 8; j++)
                    acc[i][j] += a[i] * wv[j];
        }
        __syncthreads();
    }

#pragma unroll
    for (int i = 0; i < 4; i++) {
        int r = m0 + tm + i;
        if (r >= cnt) continue;
        int ksr = g_kslot[e * T_TOK + r];
        float* yrow = g_y + (size_t)ksr * DIM;
#pragma unroll
        for (int j4 = 0; j4 < 2; j4++) {
            int n = n0 + tn + j4 * 4;
            float4 o;
            o.x = acc[i][j4 * 4 + 0] + b2[e * DIM + n + 0];
            o.y = acc[i][j4 * 4 + 1] + b2[e * DIM + n + 1];
            o.z = acc[i][j4 * 4 + 2] + b2[e * DIM + n + 2];
            o.w = acc[i][j4 * 4 + 3] + b2[e * DIM + n + 3];
            *(float4*)(yrow + n) = o;
        }
    }
}

// ---------------- combine: out[t] = w0*y[t,0] + w1*y[t,1] (fully writes d_out) ----------------
__global__ void combine_kernel(float* __restrict__ out) {
    int i = blockIdx.x * blockDim.x + threadIdx.x;   // float4 index
    if (i >= T_TOK * DIM / 4) return;
    int t  = i / (DIM / 4);
    int d4 = i % (DIM / 4);
    float w0 = g_topw[t * 2];
    float w1 = g_topw[t * 2 + 1];
    float4 y0 = *(const float4*)(g_y + (size_t)(t * 2)     * DIM + d4 * 4);
    float4 y1 = *(const float4*)(g_y + (size_t)(t * 2 + 1) * DIM + d4 * 4);
    float4 o;
    o.x = w0 * y0.x + w1 * y1.x;
    o.y = w0 * y0.y + w1 * y1.y;
    o.z = w0 * y0.z + w1 * y1.z;
    o.w = w0 * y0.w + w1 * y1.w;
    ((float4*)out)[i] = o;
}

// ---------------- launch ----------------
extern "C" void kernel_launch(void* const* d_in, const int* in_sizes, int n_in,
                              void* d_out, int out_size) {
    const float* x  = (const float*)d_in[0];
    const float* gw = (const float*)d_in[1];
    const float* gb = (const float*)d_in[2];
    const float* wg = (const float*)d_in[3];
    const float* bg = (const float*)d_in[4];
    const float* w1 = (const float*)d_in[5];
    const float* b1 = (const float*)d_in[6];
    const float* w2 = (const float*)d_in[7];
    const float* b2 = (const float*)d_in[8];
    float* out = (float*)d_out;

    init_kernel<<<1, 32>>>();
    gate_kernel<<<T_TOK / 4, 128>>>(x, gw, gb);

    dim3 g1((NH + BN - 1) / BN, T_TOK / BM, NE);   // 22 x 64 x 8 (capacity; early-exit)
    ffn1_kernel<<<g1, 256>>>(x, wg, bg, w1, b1);

    dim3 g2(DIM / BN, T_TOK / BM, NE);             // 8 x 64 x 8
    ffn2_kernel<<<g2, 256>>>(w2, b2);

    combine_kernel<<<(T_TOK * DIM / 4 + 255) / 256, 256>>>(out);
}

// round 2
// speedup vs baseline: 3.7461x; 3.7461x over previous
#include <cuda_runtime.h>
#include <math.h>

#define T_TOK 4096
#define DIM   1024
#define NE    8
#define NH    2736

#define SA_S  20     // SMEM A row stride (floats), conflict-free frag loads
#define SB_S  136    // SMEM B row stride (floats), conflict-free frag loads
#define A_WORDS (2*128*SA_S)          // 5120
#define B_WORDS (2*16*SB_S)           // 4352
#define SM_WORDS (A_WORDS + B_WORDS)  // 9472 words = 37888 B

// ---------------- scratch (static device globals; no allocations) ----------------
__device__ int   g_counts[NE];
__device__ int   g_list [NE * T_TOK];
__device__ int   g_kslot[NE * T_TOK];
__device__ float g_topw [T_TOK * 2];
__device__ float g_h[(size_t)T_TOK * 2 * NH];
__device__ float g_y[(size_t)T_TOK * 2 * DIM];

// ---------------- helpers ----------------
__device__ __forceinline__ unsigned f2tf(float x) {
    unsigned r;
    asm("cvt.rna.tf32.f32 %0, %1;" : "=r"(r) : "f"(x));
    return r;
}
__device__ __forceinline__ void mma8(float* c, const unsigned* a, const unsigned* b) {
    asm volatile(
        "mma.sync.aligned.m16n8k8.row.col.f32.tf32.tf32.f32 "
        "{%0,%1,%2,%3}, {%4,%5,%6,%7}, {%8,%9}, {%0,%1,%2,%3};"
        : "+f"(c[0]), "+f"(c[1]), "+f"(c[2]), "+f"(c[3])
        : "r"(a[0]), "r"(a[1]), "r"(a[2]), "r"(a[3]), "r"(b[0]), "r"(b[1]));
}

// ---------------- init ----------------
__global__ void init_kernel() {
    if (threadIdx.x < NE) g_counts[threadIdx.x] = 0;
}

// ---------------- gating: one warp per token ----------------
__global__ void gate_kernel(const float* __restrict__ x,
                            const float* __restrict__ gw,
                            const float* __restrict__ gb) {
    int lane = threadIdx.x & 31;
    int w    = threadIdx.x >> 5;
    int t    = blockIdx.x * (blockDim.x >> 5) + w;
    if (t >= T_TOK) return;

    float acc[NE];
#pragma unroll
    for (int e = 0; e < NE; e++) acc[e] = 0.f;

    const float* xr = x + (size_t)t * DIM;
    for (int d = lane; d < DIM; d += 32) {
        float xv = __ldg(xr + d);
        const float4* g4 = (const float4*)(gw + d * NE);
        float4 a = __ldg(g4);
        float4 b = __ldg(g4 + 1);
        acc[0] += xv * a.x; acc[1] += xv * a.y; acc[2] += xv * a.z; acc[3] += xv * a.w;
        acc[4] += xv * b.x; acc[5] += xv * b.y; acc[6] += xv * b.z; acc[7] += xv * b.w;
    }
#pragma unroll
    for (int e = 0; e < NE; e++) {
#pragma unroll
        for (int off = 16; off > 0; off >>= 1)
            acc[e] += __shfl_xor_sync(0xffffffffu, acc[e], off);
    }

    if (lane == 0) {
        float v0 = -1e30f, v1 = -1e30f;
        int   i0 = 0,      i1 = 0;
#pragma unroll
        for (int e = 0; e < NE; e++) {
            float v = acc[e] + gb[e];
            if (v > v0)      { v1 = v0; i1 = i0; v0 = v; i0 = e; }
            else if (v > v1) { v1 = v;  i1 = e; }
        }
        float w0 = 1.f / (1.f + expf(v1 - v0));
        float w1 = 1.f - w0;
        g_topw[t * 2]     = w0;
        g_topw[t * 2 + 1] = w1;
        int p0 = atomicAdd(&g_counts[i0], 1);
        g_list [i0 * T_TOK + p0] = t;
        g_kslot[i0 * T_TOK + p0] = t * 2;
        int p1 = atomicAdd(&g_counts[i1], 1);
        g_list [i1 * T_TOK + p1] = t;
        g_kslot[i1 * T_TOK + p1] = t * 2 + 1;
    }
}

// ================= FFN1: h = silu(x@wg+bg) * (x@w1+b1)  (tf32 tensor cores) =================
// Block: 128 rows x 64 H-cols (accum tile 128x128: cols 0-63 gate, 64-127 lin)
__global__ __launch_bounds__(256)
void ffn1_kernel(const float* __restrict__ x,
                 const float* __restrict__ wg, const float* __restrict__ bgp,
                 const float* __restrict__ w1, const float* __restrict__ b1p) {
    int e   = blockIdx.z;
    int cnt = g_counts[e];
    int m0  = blockIdx.y * 128;
    if (m0 >= cnt) return;
    int n0  = blockIdx.x * 64;
    int tid = threadIdx.x;

    __shared__ __align__(16) unsigned smemraw[SM_WORDS];

    // ---- A (gathered x) load mapping: row = tid>>1 (0..127), 2 float4 at cols (tid&1)*8, +4
    int  ar   = tid >> 1;
    int  ac   = (tid & 1) * 8;
    bool av   = (m0 + ar) < cnt;
    const float* xrow = x + (size_t)(av ? g_list[e * T_TOK + m0 + ar] : 0) * DIM;

    // ---- B load mapping: row = tid>>4 (0..15), col4 = (tid&15)*4 (0..60); gate->col, lin->col+64
    int  br   = tid >> 4;
    int  bc   = (tid & 15) * 4;
    bool bv   = (n0 + bc) < NH;               // NH%4==0 -> float4-granular safe
    const float* wgp = wg + (size_t)e * DIM * NH + n0 + bc;
    const float* w1p = w1 + (size_t)e * DIM * NH + n0 + bc;

    const float4 z4 = make_float4(0.f, 0.f, 0.f, 0.f);
    float4 ra0, ra1, rbg, rbl;

    // stage 0 loads
    ra0 = av ? *(const float4*)(xrow + ac)     : z4;
    ra1 = av ? *(const float4*)(xrow + ac + 4) : z4;
    rbg = bv ? *(const float4*)(wgp + (size_t)br * NH) : z4;
    rbl = bv ? *(const float4*)(w1p + (size_t)br * NH) : z4;

    unsigned* sA0 = smemraw;
    unsigned* sB0 = smemraw + A_WORDS;

#define STS_A(buf)  do { unsigned* p = sA0 + (buf)*128*SA_S + ar*SA_S + ac;            \
        p[0]=f2tf(ra0.x); p[1]=f2tf(ra0.y); p[2]=f2tf(ra0.z); p[3]=f2tf(ra0.w);        \
        p[4]=f2tf(ra1.x); p[5]=f2tf(ra1.y); p[6]=f2tf(ra1.z); p[7]=f2tf(ra1.w); } while(0)
#define STS_B1(buf) do { unsigned* p = sB0 + (buf)*16*SB_S + br*SB_S + bc;             \
        p[0]=f2tf(rbg.x); p[1]=f2tf(rbg.y); p[2]=f2tf(rbg.z); p[3]=f2tf(rbg.w);        \
        p[64]=f2tf(rbl.x); p[65]=f2tf(rbl.y); p[66]=f2tf(rbl.z); p[67]=f2tf(rbl.w); } while(0)

    STS_A(0); STS_B1(0);
    __syncthreads();

    float c[2][8][4];
#pragma unroll
    for (int i = 0; i < 2; i++)
#pragma unroll
        for (int j = 0; j < 8; j++)
#pragma unroll
            for (int q = 0; q < 4; q++) c[i][j][q] = 0.f;

    int warp = tid >> 5, lane = tid & 31;
    int wm = (warp >> 1) * 32;
    int wn = (warp & 1) * 64;
    int fr = lane >> 2;       // fragment row within 8
    int fc = lane & 3;        // fragment col within 4

    const int NIT = DIM / 16;  // 64
    for (int it = 0; it < NIT; it++) {
        if (it + 1 < NIT) {
            int k0 = (it + 1) * 16;
            ra0 = av ? *(const float4*)(xrow + k0 + ac)     : z4;
            ra1 = av ? *(const float4*)(xrow + k0 + ac + 4) : z4;
            rbg = bv ? *(const float4*)(wgp + (size_t)(k0 + br) * NH) : z4;
            rbl = bv ? *(const float4*)(w1p + (size_t)(k0 + br) * NH) : z4;
        }
        const unsigned* sA = sA0 + (it & 1) * 128 * SA_S;
        const unsigned* sB = sB0 + (it & 1) * 16 * SB_S;
#pragma unroll
        for (int ks = 0; ks < 2; ks++) {
            int k8 = ks * 8;
            unsigned af[2][4];
#pragma unroll
            for (int mt = 0; mt < 2; mt++) {
                const unsigned* p = sA + (wm + mt * 16 + fr) * SA_S + k8 + fc;
                af[mt][0] = p[0];
                af[mt][1] = p[8 * SA_S];
                af[mt][2] = p[4];
                af[mt][3] = p[8 * SA_S + 4];
            }
#pragma unroll
            for (int nt = 0; nt < 8; nt++) {
                const unsigned* q = sB + (k8 + fc) * SB_S + wn + nt * 8 + fr;
                unsigned bf[2] = { q[0], q[4 * SB_S] };
                mma8(c[0][nt], af[0], bf);
                mma8(c[1][nt], af[1], bf);
            }
        }
        if (it + 1 < NIT) {
            STS_A((it + 1) & 1); STS_B1((it + 1) & 1);
            __syncthreads();
        }
    }

    // ---- epilogue: exchange gate half through SMEM, lin warps apply activation ----
    __syncthreads();
    float* ex = (float*)smemraw;   // [128][66]
    if (wn == 0) {
#pragma unroll
        for (int mt = 0; mt < 2; mt++)
#pragma unroll
            for (int nt = 0; nt < 8; nt++) {
                int r  = wm + mt * 16 + fr;
                int cc = nt * 8 + 2 * fc;
                ex[r * 66 + cc]           = c[mt][nt][0];
                ex[r * 66 + cc + 1]       = c[mt][nt][1];
                ex[(r + 8) * 66 + cc]     = c[mt][nt][2];
                ex[(r + 8) * 66 + cc + 1] = c[mt][nt][3];
            }
    }
    __syncthreads();
    if (wn == 64) {
#pragma unroll
        for (int mt = 0; mt < 2; mt++)
#pragma unroll
            for (int nt = 0; nt < 8; nt++) {
                int cc = nt * 8 + 2 * fc;
                int n  = n0 + cc;
                if (n >= NH) continue;
                float bgv0 = bgp[e * NH + n],     bgv1 = bgp[e * NH + n + 1];
                float blv0 = b1p[e * NH + n],     blv1 = b1p[e * NH + n + 1];
#pragma unroll
                for (int half = 0; half < 2; half++) {
                    int r = wm + mt * 16 + fr + half * 8;
                    if (m0 + r >= cnt) continue;
                    int ks = g_kslot[e * T_TOK + m0 + r];
                    float gv0 = ex[r * 66 + cc]     + bgv0;
                    float gv1 = ex[r * 66 + cc + 1] + bgv1;
                    float lv0 = c[mt][nt][half * 2]     + blv0;
                    float lv1 = c[mt][nt][half * 2 + 1] + blv1;
                    float h0 = (gv0 / (1.f + expf(-gv0))) * lv0;
                    float h1 = (gv1 / (1.f + expf(-gv1))) * lv1;
                    float2 hv = make_float2(h0, h1);
                    *(float2*)(g_h + (size_t)ks * NH + n) = hv;
                }
            }
    }
#undef STS_A
#undef STS_B1
}

// ================= FFN2: y = h @ w2 + b2  (tf32 tensor cores) =================
// Block: 128 rows x 128 D-cols
__global__ __launch_bounds__(256)
void ffn2_kernel(const float* __restrict__ w2, const float* __restrict__ b2p) {
    int e   = blockIdx.z;
    int cnt = g_counts[e];
    int m0  = blockIdx.y * 128;
    if (m0 >= cnt) return;
    int n0  = blockIdx.x * 128;
    int tid = threadIdx.x;

    __shared__ __align__(16) unsigned smemraw[SM_WORDS];

    int  ar = tid >> 1;
    int  ac = (tid & 1) * 8;
    bool av = (m0 + ar) < cnt;
    const float* hrow = g_h + (size_t)(av ? g_kslot[e * T_TOK + m0 + ar] : 0) * NH;

    // B: 16x128 tile, thread loads 2 float4: rows tid>>5 and +8, col (tid&31)*4
    int  br = tid >> 5;
    int  bc = (tid & 31) * 4;
    const float* w2p = w2 + (size_t)e * NH * DIM + n0 + bc;

    const float4 z4 = make_float4(0.f, 0.f, 0.f, 0.f);
    float4 ra0, ra1, rb0, rb1;

    ra0 = av ? *(const float4*)(hrow + ac)     : z4;
    ra1 = av ? *(const float4*)(hrow + ac + 4) : z4;
    rb0 = *(const float4*)(w2p + (size_t)br * DIM);
    rb1 = *(const float4*)(w2p + (size_t)(br + 8) * DIM);

    unsigned* sA0 = smemraw;
    unsigned* sB0 = smemraw + A_WORDS;

#define STS_A2(buf) do { unsigned* p = sA0 + (buf)*128*SA_S + ar*SA_S + ac;            \
        p[0]=f2tf(ra0.x); p[1]=f2tf(ra0.y); p[2]=f2tf(ra0.z); p[3]=f2tf(ra0.w);        \
        p[4]=f2tf(ra1.x); p[5]=f2tf(ra1.y); p[6]=f2tf(ra1.z); p[7]=f2tf(ra1.w); } while(0)
#define STS_B2(buf) do { unsigned* p = sB0 + (buf)*16*SB_S + br*SB_S + bc;             \
        p[0]=f2tf(rb0.x); p[1]=f2tf(rb0.y); p[2]=f2tf(rb0.z); p[3]=f2tf(rb0.w);        \
        unsigned* p2 = p + 8*SB_S;                                                     \
        p2[0]=f2tf(rb1.x); p2[1]=f2tf(rb1.y); p2[2]=f2tf(rb1.z); p2[3]=f2tf(rb1.w); } while(0)

    STS_A2(0); STS_B2(0);
    __syncthreads();

    float c[2][8][4];
#pragma unroll
    for (int i = 0; i < 2; i++)
#pragma unroll
        for (int j = 0; j < 8; j++)
#pragma unroll
            for (int q = 0; q < 4; q++) c[i][j][q] = 0.f;

    int warp = tid >> 5, lane = tid & 31;
    int wm = (warp >> 1) * 32;
    int wn = (warp & 1) * 64;
    int fr = lane >> 2;
    int fc = lane & 3;

    const int NIT = NH / 16;   // 171
    for (int it = 0; it < NIT; it++) {
        if (it + 1 < NIT) {
            int k0 = (it + 1) * 16;
            ra0 = av ? *(const float4*)(hrow + k0 + ac)     : z4;
            ra1 = av ? *(const float4*)(hrow + k0 + ac + 4) : z4;
            rb0 = *(const float4*)(w2p + (size_t)(k0 + br) * DIM);
            rb1 = *(const float4*)(w2p + (size_t)(k0 + br + 8) * DIM);
        }
        const unsigned* sA = sA0 + (it & 1) * 128 * SA_S;
        const unsigned* sB = sB0 + (it & 1) * 16 * SB_S;
#pragma unroll
        for (int ks = 0; ks < 2; ks++) {
            int k8 = ks * 8;
            unsigned af[2][4];
#pragma unroll
            for (int mt = 0; mt < 2; mt++) {
                const unsigned* p = sA + (wm + mt * 16 + fr) * SA_S + k8 + fc;
                af[mt][0] = p[0];
                af[mt][1] = p[8 * SA_S];
                af[mt][2] = p[4];
                af[mt][3] = p[8 * SA_S + 4];
            }
#pragma unroll
            for (int nt = 0; nt < 8; nt++) {
                const unsigned* q = sB + (k8 + fc) * SB_S + wn + nt * 8 + fr;
                unsigned bf[2] = { q[0], q[4 * SB_S] };
                mma8(c[0][nt], af[0], bf);
                mma8(c[1][nt], af[1], bf);
            }
        }
        if (it + 1 < NIT) {
            STS_A2((it + 1) & 1); STS_B2((it + 1) & 1);
            __syncthreads();
        }
    }

    // epilogue: y = c + b2, float2 stores
#pragma unroll
    for (int mt = 0; mt < 2; mt++)
#pragma unroll
        for (int nt = 0; nt < 8; nt++) {
            int cc = wn + nt * 8 + 2 * fc;
            int n  = n0 + cc;
            float b0 = b2p[e * DIM + n], b1v = b2p[e * DIM + n + 1];
#pragma unroll
            for (int half = 0; half < 2; half++) {
                int r = wm + mt * 16 + fr + half * 8;
                if (m0 + r >= cnt) continue;
                int ks = g_kslot[e * T_TOK + m0 + r];
                float2 yv = make_float2(c[mt][nt][half * 2] + b0,
                                        c[mt][nt][half * 2 + 1] + b1v);
                *(float2*)(g_y + (size_t)ks * DIM + n) = yv;
            }
        }
#undef STS_A2
#undef STS_B2
}

// ---------------- combine ----------------
__global__ void combine_kernel(float* __restrict__ out) {
    int i = blockIdx.x * blockDim.x + threadIdx.x;
    if (i >= T_TOK * DIM / 4) return;
    int t  = i / (DIM / 4);
    int d4 = i % (DIM / 4);
    float w0 = g_topw[t * 2];
    float w1 = g_topw[t * 2 + 1];
    float4 y0 = *(const float4*)(g_y + (size_t)(t * 2)     * DIM + d4 * 4);
    float4 y1 = *(const float4*)(g_y + (size_t)(t * 2 + 1) * DIM + d4 * 4);
    float4 o;
    o.x = w0 * y0.x + w1 * y1.x;
    o.y = w0 * y0.y + w1 * y1.y;
    o.z = w0 * y0.z + w1 * y1.z;
    o.w = w0 * y0.w + w1 * y1.w;
    ((float4*)out)[i] = o;
}

// ---------------- launch ----------------
extern "C" void kernel_launch(void* const* d_in, const int* in_sizes, int n_in,
                              void* d_out, int out_size) {
    const float* x  = (const float*)d_in[0];
    const float* gw = (const float*)d_in[1];
    const float* gb = (const float*)d_in[2];
    const float* wg = (const float*)d_in[3];
    const float* bg = (const float*)d_in[4];
    const float* w1 = (const float*)d_in[5];
    const float* b1 = (const float*)d_in[6];
    const float* w2 = (const float*)d_in[7];
    const float* b2 = (const float*)d_in[8];
    float* out = (float*)d_out;

    init_kernel<<<1, 32>>>();
    gate_kernel<<<T_TOK / 4, 128>>>(x, gw, gb);

    dim3 g1((NH + 63) / 64, T_TOK / 128, NE);     // 43 x 32 x 8, early-exit
    ffn1_kernel<<<g1, 256>>>(x, wg, bg, w1, b1);

    dim3 g2(DIM / 128, T_TOK / 128, NE);          // 8 x 32 x 8
    ffn2_kernel<<<g2, 256>>>(w2, b2);

    combine_kernel<<<(T_TOK * DIM / 4 + 255) / 256, 256>>>(out);
}